// round 3
// baseline (speedup 1.0000x reference)
#include <cuda_runtime.h>
#include <cstdint>
#include <cstddef>

// Problem constants (shapes fixed by the dataset)
#define Nn 65536
#define Dd 256
#define Kk 4096
#define DECAYF 0.99f
#define BETAF 0.25f
#define EPSF 1e-5f

// Argmin-GEMM tiling
#define BM 128       // rows of z per block
#define KT 128       // codebook columns per k-tile
#define BD 64        // d-chunk streamed per cp.async stage
#define WBUF (BD*KT) // floats per weight buffer
#define NCHUNK ((Kk/KT)*(Dd/BD))   // 128

// -------- scratch (static device globals; no dynamic allocation) --------
__device__ __align__(16) float g_wt[(size_t)Dd * Kk];   // W transposed: [d][k]
__device__ __align__(16) float g_wsq[Kk];
__device__ __align__(16) int   g_idx[Nn];
__device__ __align__(16) float g_counts[Kk];
__device__ __align__(16) float g_dw[(size_t)Kk * Dd];
__device__ __align__(16) float g_cs[Kk];
__device__ __align__(16) float g_red[4];

// ---------------------------------------------------------------
// 1) transpose W [K][D] -> g_wt [D][K]
// ---------------------------------------------------------------
__global__ void transpose_kernel(const float* __restrict__ W) {
    __shared__ float t[32][33];
    int k0 = blockIdx.x * 32, d0 = blockIdx.y * 32;
    int x = threadIdx.x, y = threadIdx.y;   // 32 x 8
#pragma unroll
    for (int r = 0; r < 4; ++r)
        t[y + 8 * r][x] = W[(size_t)(k0 + y + 8 * r) * Dd + d0 + x];
    __syncthreads();
#pragma unroll
    for (int r = 0; r < 4; ++r)
        g_wt[(size_t)(d0 + y + 8 * r) * Kk + k0 + x] = t[x][y + 8 * r];
}

// ---------------------------------------------------------------
// 2) wsq[k] = sum_d W[k][d]^2   (one 256-thread block per row)
// ---------------------------------------------------------------
__global__ void wsq_kernel(const float* __restrict__ W) {
    __shared__ float s[8];
    int k = blockIdx.x, t = threadIdx.x;
    float v = W[(size_t)k * Dd + t];
    v *= v;
#pragma unroll
    for (int o = 16; o; o >>= 1) v += __shfl_xor_sync(0xffffffffu, v, o);
    if ((t & 31) == 0) s[t >> 5] = v;
    __syncthreads();
    if (t < 8) {
        float x = s[t];
#pragma unroll
        for (int o = 4; o; o >>= 1) x += __shfl_xor_sync(0xffu, x, o);
        if (t == 0) g_wsq[k] = x;
    }
}

// ---------------------------------------------------------------
// 3) fused distance + argmin (the heavy kernel)
//    dist(n,k) = wsq[k] - 2 * z[n].W[k]   (||z||^2 is argmin-invariant)
// ---------------------------------------------------------------
__device__ __forceinline__ void issue_chunk(float* ws, int c, int b, int tid) {
    const float* src = g_wt + (size_t)((c & 3) * BD) * Kk + (size_t)(c >> 2) * KT;
    float* dst = ws + b * WBUF;
#pragma unroll
    for (int i = 0; i < 8; ++i) {
        int q = tid + i * 256;
        int row = q >> 5, col = (q & 31) * 4;
        unsigned sa = (unsigned)__cvta_generic_to_shared(dst + row * KT + col);
        const float* gp = src + (size_t)row * Kk + col;
        asm volatile("cp.async.cg.shared.global [%0], [%1], 16;" :: "r"(sa), "l"(gp));
    }
    asm volatile("cp.async.commit_group;");
}

__global__ __launch_bounds__(256, 1)
void argmin_kernel(const float* __restrict__ z) {
    extern __shared__ float smem[];
    float* zs = smem;                 // [BM][Dd]  (128 KB)
    float* ws = smem + BM * Dd;       // [2][BD][KT] (64 KB)
    int tid = threadIdx.x;
    int tx = tid & 15, ty = tid >> 4;
    int m0 = blockIdx.x * BM;

    issue_chunk(ws, 0, 0, tid);

    // z tile -> smem, coalesced float4 copy
    const float4* zg = (const float4*)(z + (size_t)m0 * Dd);
    float4* zs4 = (float4*)zs;
#pragma unroll
    for (int i = 0; i < 32; ++i) zs4[tid + (i << 8)] = zg[tid + (i << 8)];

    // accumulators: 8 m-rows x 4 k-pairs (f32x2 packed along k)
    unsigned long long acc[8][4];
#pragma unroll
    for (int i = 0; i < 8; ++i)
#pragma unroll
        for (int j = 0; j < 4; ++j) acc[i][j] = 0ull;

    float best_v[8];
    int best_i[8];
#pragma unroll
    for (int i = 0; i < 8; ++i) { best_v[i] = 3.4e38f; best_i[i] = 0; }

    for (int c = 0; c < NCHUNK; ++c) {
        int b = c & 1;
        if (c + 1 < NCHUNK) {
            issue_chunk(ws, c + 1, b ^ 1, tid);
            asm volatile("cp.async.wait_group 1;");
        } else {
            asm volatile("cp.async.wait_group 0;");
        }
        __syncthreads();

        const float* wb = ws + b * WBUF;
        int dg0 = (c & 3) * BD;
#pragma unroll 4
        for (int d = 0; d < BD; ++d) {
            unsigned long long bf[4];
#pragma unroll
            for (int jp = 0; jp < 4; ++jp)
                bf[jp] = *(const unsigned long long*)(wb + d * KT + 2 * tx + 32 * jp);
#pragma unroll
            for (int i = 0; i < 8; ++i) {
                float a = zs[(ty * 8 + i) * Dd + dg0 + d];
                unsigned long long a2;
                asm("mov.b64 %0, {%1, %1};" : "=l"(a2) : "f"(a));
#pragma unroll
                for (int jp = 0; jp < 4; ++jp)
                    asm("fma.rn.f32x2 %0, %1, %2, %0;"
                        : "+l"(acc[i][jp]) : "l"(a2), "l"(bf[jp]));
            }
        }

        if ((c & 3) == 3) {  // finished K-tile: fold into running argmin
            int k0 = (c >> 2) * KT;
            float wq[8];
#pragma unroll
            for (int jp = 0; jp < 4; ++jp) {
                int kk = k0 + 2 * tx + 32 * jp;
                wq[2 * jp] = __ldg(&g_wsq[kk]);
                wq[2 * jp + 1] = __ldg(&g_wsq[kk + 1]);
            }
#pragma unroll
            for (int i = 0; i < 8; ++i) {
                float v = 3.4e38f; int vi = 0;
#pragma unroll
                for (int jp = 0; jp < 4; ++jp) {
                    float lo, hi;
                    asm("mov.b64 {%0, %1}, %2;" : "=f"(lo), "=f"(hi) : "l"(acc[i][jp]));
                    int kk = k0 + 2 * tx + 32 * jp;
                    float d0 = wq[2 * jp] - 2.0f * lo;
                    float d1 = wq[2 * jp + 1] - 2.0f * hi;
                    if (d0 < v) { v = d0; vi = kk; }
                    if (d1 < v) { v = d1; vi = kk + 1; }
                    acc[i][jp] = 0ull;
                }
                // reduce across the 16 k-lanes (bfly keeps all lanes consistent)
#pragma unroll
                for (int off = 8; off > 0; off >>= 1) {
                    float ov = __shfl_xor_sync(0xffffffffu, v, off);
                    int oi = __shfl_xor_sync(0xffffffffu, vi, off);
                    if (ov < v || (ov == v && oi < vi)) { v = ov; vi = oi; }
                }
                if (v < best_v[i]) { best_v[i] = v; best_i[i] = vi; }
            }
        }
        __syncthreads();
    }

    if (tx == 0) {
#pragma unroll
        for (int i = 0; i < 8; ++i) {
            int m = m0 + ty * 8 + i;
            g_idx[m] = best_i[i];
            atomicAdd(&g_counts[best_i[i]], 1.0f);
        }
    }
}

// ---------------------------------------------------------------
// 4) dw[k] += z[n] for idx[n]==k  (one warp per row)
// ---------------------------------------------------------------
__global__ void scatter_kernel(const float* __restrict__ z) {
    int n = (blockIdx.x * blockDim.x + threadIdx.x) >> 5;
    int lane = threadIdx.x & 31;
    int k = g_idx[n];
    const float* zr = z + (size_t)n * Dd;
    float* dr = g_dw + (size_t)k * Dd;
#pragma unroll
    for (int j = 0; j < 8; ++j)
        atomicAdd(dr + lane + 32 * j, zr[lane + 32 * j]);
}

// ---------------------------------------------------------------
// 5) cluster-size EMA + Laplace smoothing + perplexity (1 block)
// ---------------------------------------------------------------
__global__ void finalize_cs_kernel(const float* __restrict__ cs_in,
                                   float* __restrict__ out_cs,
                                   float* __restrict__ out_perp) {
    __shared__ float s1[256], s2[256];
    int t = threadIdx.x;
    float scs = 0.f, se = 0.f;
    float csr[16];
#pragma unroll
    for (int i = 0; i < 16; ++i) {
        int k = t + i * 256;
        float cnt = g_counts[k];
        float r = cs_in[k] * DECAYF + (1.0f - DECAYF) * cnt;
        csr[i] = r;
        scs += r;
        float p = cnt * (1.0f / (float)Nn);
        se += p * logf(p + 1e-10f);
    }
    s1[t] = scs; s2[t] = se;
    __syncthreads();
    for (int o = 128; o; o >>= 1) {
        if (t < o) { s1[t] += s1[t + o]; s2[t] += s2[t + o]; }
        __syncthreads();
    }
    float n = s1[0];
    float scale = n / (n + (float)Kk * EPSF);
#pragma unroll
    for (int i = 0; i < 16; ++i) {
        int k = t + i * 256;
        float cf = (csr[i] + EPSF) * scale;
        g_cs[k] = cf;
        out_cs[k] = cf;
    }
    if (t == 0) out_perp[0] = expf(-s2[0]);
}

// ---------------------------------------------------------------
// 6) EMA weight + normalized codebook
// ---------------------------------------------------------------
__global__ void update_w_kernel(const float* __restrict__ ema,
                                float* __restrict__ out_ema,
                                float* __restrict__ out_w) {
    int i = blockIdx.x * 256 + threadIdx.x;
    float e = ema[i] * DECAYF + (1.0f - DECAYF) * g_dw[i];
    out_ema[i] = e;
    out_w[i] = e / g_cs[i >> 8];
}

// ---------------------------------------------------------------
// 7) z_q gather (STE) + loss partial + idx as float (warp per row)
// ---------------------------------------------------------------
__global__ void gather_loss_kernel(const float* __restrict__ z,
                                   const float* __restrict__ w_new,
                                   float* __restrict__ out_zq,
                                   float* __restrict__ out_idx) {
    int n = (blockIdx.x * blockDim.x + threadIdx.x) >> 5;
    int lane = threadIdx.x & 31;
    int k = g_idx[n];
    const float* wr = w_new + (size_t)k * Dd;
    const float* zr = z + (size_t)n * Dd;
    float* qr = out_zq + (size_t)n * Dd;
    float part = 0.f;
#pragma unroll
    for (int j = 0; j < 8; ++j) {
        int dd = lane + 32 * j;
        float wv = wr[dd], zv = zr[dd];
        float tdiff = wv - zv;          // stop_gradient(z_q - z)
        qr[dd] = zv + tdiff;            // z + (z_q - z), matches jax STE arithmetic
        part += tdiff * tdiff;
    }
#pragma unroll
    for (int o = 16; o; o >>= 1) part += __shfl_xor_sync(0xffffffffu, part, o);
    if (lane == 0) {
        out_idx[n] = (float)k;
        atomicAdd(&g_red[0], part);
    }
}

__global__ void loss_kernel(float* __restrict__ out_loss) {
    out_loss[0] = (1.0f + BETAF) * g_red[0] / (float)((size_t)Nn * Dd);
}

// ---------------------------------------------------------------
// host launcher
// ---------------------------------------------------------------
extern "C" void kernel_launch(void* const* d_in, const int* in_sizes, int n_in,
                              void* d_out, int out_size) {
    const float* z   = (const float*)d_in[0];
    const float* W   = (const float*)d_in[1];
    const float* ema = (const float*)d_in[2];
    const float* cs  = (const float*)d_in[3];
    float* out = (float*)d_out;

    const size_t off_idx  = (size_t)Nn * Dd;
    const size_t off_loss = off_idx + Nn;
    const size_t off_perp = off_loss + 1;
    const size_t off_cs   = off_perp + 1;
    const size_t off_emaw = off_cs + Kk;
    const size_t off_w    = off_emaw + (size_t)Kk * Dd;

    void *p_counts, *p_dw, *p_red;
    cudaGetSymbolAddress(&p_counts, g_counts);
    cudaGetSymbolAddress(&p_dw, g_dw);
    cudaGetSymbolAddress(&p_red, g_red);
    cudaMemsetAsync(p_counts, 0, Kk * sizeof(float));
    cudaMemsetAsync(p_dw, 0, (size_t)Kk * Dd * sizeof(float));
    cudaMemsetAsync(p_red, 0, 4 * sizeof(float));

    const int smem_bytes = (BM * Dd + 2 * WBUF) * (int)sizeof(float);  // 192 KB
    cudaFuncSetAttribute(argmin_kernel, cudaFuncAttributeMaxDynamicSharedMemorySize,
                         smem_bytes);

    transpose_kernel<<<dim3(Kk / 32, Dd / 32), dim3(32, 8)>>>(W);
    wsq_kernel<<<Kk, 256>>>(W);
    argmin_kernel<<<Nn / BM, 256, smem_bytes>>>(z);
    scatter_kernel<<<Nn / 8, 256>>>(z);
    finalize_cs_kernel<<<1, 256>>>(cs, out + off_cs, out + off_perp);
    update_w_kernel<<<(Kk * Dd) / 256, 256>>>(ema, out + off_emaw, out + off_w);
    gather_loss_kernel<<<Nn / 8, 256>>>(z, out + off_w, out, out + off_idx);
    loss_kernel<<<1, 1>>>(out + off_loss);
}

// round 11
// speedup vs baseline: 1.0510x; 1.0510x over previous
#include <cuda_runtime.h>
#include <cuda_bf16.h>
#include <cstdint>
#include <cstddef>

#define Nn 65536
#define Dd 256
#define Kk 4096
#define DECAYF 0.99f
#define BETAF 0.25f
#define EPSF 1e-5f
#define GAPT 0.05f

// ---- smem map (bytes), BM=64, no swizzle, padded strides ----
// A_hi [0, 64*528)   A_lo [33792, 67584)
// B    [67584, 67584 + 2*33280)   (rows of 1040 B: hi 512 | lo 512 | pad 16)
// wsq  [134144, 150528)
// merge [150528, 153600): mv[64][4], mv2[64][4], mvi[64][4]
#define A_STRIDE 528u
#define A_LO_OFF 33792u
#define B_OFF    67584u
#define B_STRIDE 1040u
#define BTILE    33280u
#define WSQ_OFF  134144u
#define MRG_OFF  150528u
#define SMEM_BYTES 153600u
#define NTILES 128   // 4096 / 32 codes per tile

__device__ __forceinline__ uint32_t smem_u32(const void* p) {
    uint32_t a;
    asm("{ .reg .u64 t; cvta.to.shared.u64 t, %1; cvt.u32.u64 %0, t; }" : "=r"(a) : "l"(p));
    return a;
}
#define LDSM_X4(r, a) asm volatile( \
    "ldmatrix.sync.aligned.m8n8.x4.shared.b16 {%0,%1,%2,%3}, [%4];" \
    : "=r"((r)[0]), "=r"((r)[1]), "=r"((r)[2]), "=r"((r)[3]) : "r"(a))
#define LDSM_X2(r, a) asm volatile( \
    "ldmatrix.sync.aligned.m8n8.x2.shared.b16 {%0,%1}, [%2];" \
    : "=r"((r)[0]), "=r"((r)[1]) : "r"(a))
#define MMA_BF16(d, a, b0, b1) asm volatile( \
    "mma.sync.aligned.m16n8k16.row.col.f32.bf16.bf16.f32 " \
    "{%0,%1,%2,%3}, {%4,%5,%6,%7}, {%8,%9}, {%0,%1,%2,%3};" \
    : "+f"((d)[0]), "+f"((d)[1]), "+f"((d)[2]), "+f"((d)[3]) \
    : "r"((a)[0]), "r"((a)[1]), "r"((a)[2]), "r"((a)[3]), "r"(b0), "r"(b1))

// ============ scratch globals ============
__device__ __align__(128) __nv_bfloat16 g_bs[(size_t)Kk * 512]; // [k][hi 256 | lo 256] of -2w
__device__ __align__(16) float g_wsq[Kk];
__device__ __align__(16) int   g_idx[Nn];
__device__ __align__(16) float g_counts[Kk];
__device__ __align__(16) float g_dw[(size_t)Kk * Dd];
__device__ __align__(16) float g_cs[Kk];
__device__ __align__(16) float g_red[4];
__device__ __align__(16) int   g_flag[Nn];
__device__ int g_nflag;

// ---------------- 1) prep: wsq + bf16 hi/lo split of -2W ----------------
__global__ void prep_w_kernel(const float* __restrict__ W) {
    __shared__ float s[8];
    int k = blockIdx.x, t = threadIdx.x;
    float w = W[(size_t)k * Dd + t];
    float v = w * w;
#pragma unroll
    for (int o = 16; o; o >>= 1) v += __shfl_xor_sync(0xffffffffu, v, o);
    if ((t & 31) == 0) s[t >> 5] = v;
    __syncthreads();
    if (t < 8) {
        float x = s[t];
#pragma unroll
        for (int o = 4; o; o >>= 1) x += __shfl_xor_sync(0xffu, x, o);
        if (t == 0) g_wsq[k] = x;
    }
    float m2 = -2.0f * w;
    __nv_bfloat16 h = __float2bfloat16(m2);
    __nv_bfloat16 l = __float2bfloat16(m2 - __bfloat162float(h));
    g_bs[(size_t)k * 512 + t] = h;
    g_bs[(size_t)k * 512 + 256 + t] = l;
}

// ---------------- 2) HMMA distance + argmin (64 rows/CTA) ----------------
__device__ __forceinline__ void issue_btile(uint32_t bb, int nt, int tid) {
    int k0 = nt * 32;
#pragma unroll
    for (int ii = 0; ii < 8; ++ii) {
        int q = tid + ii * 256;          // 0..2047 16B chunks
        int code = q >> 6;               // 0..31
        int ci = q & 63;                 // 16B chunk within the 1024B payload
        const char* gp = (const char*)g_bs + (((size_t)(k0 + code)) << 10) + (ci << 4);
        uint32_t sa = bb + (uint32_t)code * B_STRIDE + (uint32_t)(ci << 4);
        asm volatile("cp.async.cg.shared.global [%0], [%1], 16;" :: "r"(sa), "l"(gp));
    }
    asm volatile("cp.async.commit_group;");
}

__device__ __forceinline__ uint32_t bpack(float a, float b) {
    __nv_bfloat162 t(__float2bfloat16(a), __float2bfloat16(b));
    return *reinterpret_cast<uint32_t*>(&t);
}

// merge (ov,ov2,ovi) into (v,v2,vi); exact ties -> lower index with gap 0 (gets flagged)
__device__ __forceinline__ void amerge(float& v, float& v2, int& vi,
                                       float ov, float ov2, int ovi) {
    if (ov < v)      { v2 = fminf(v, ov2); v = ov; vi = ovi; }
    else if (ov > v) { v2 = fminf(v2, ov); }
    else             { v2 = v; vi = min(vi, ovi); }
}

__global__ __launch_bounds__(256, 1)
void mma_argmin_kernel(const float* __restrict__ z) {
    extern __shared__ char smem[];
    uint32_t sb = smem_u32(smem);
    float* wsq_s = (float*)(smem + WSQ_OFF);
    float* mv  = (float*)(smem + MRG_OFF);          // [64][4]
    float* mv2 = mv + 256;
    int*   mvi = (int*)(mv2 + 256);
    int tid = threadIdx.x, wid = tid >> 5, lane = tid & 31;
    int m0 = blockIdx.x * 64;
    int wm = wid & 1;          // 32-row half
    int wn = wid >> 1;         // 8-code slice of the 32-code tile

    issue_btile(sb + B_OFF, 0, tid);

    // z tile -> smem bf16 hi/lo, plain padded layout
    for (int idx = tid; idx < 64 * 64; idx += 256) {
        int row = idx >> 6, c4 = idx & 63;
        float4 q = ((const float4*)(z + ((size_t)(m0 + row) << 8)))[c4];
        float hx = __bfloat162float(__float2bfloat16(q.x));
        float hy = __bfloat162float(__float2bfloat16(q.y));
        float hz = __bfloat162float(__float2bfloat16(q.z));
        float hw = __bfloat162float(__float2bfloat16(q.w));
        uint32_t off = (uint32_t)row * A_STRIDE + (uint32_t)(c4 << 3);
        *(uint2*)(smem + off) = make_uint2(bpack(hx, hy), bpack(hz, hw));
        *(uint2*)(smem + A_LO_OFF + off) =
            make_uint2(bpack(q.x - hx, q.y - hy), bpack(q.z - hz, q.w - hw));
    }
    for (int i = tid; i < Kk; i += 256) wsq_s[i] = g_wsq[i];

    // ldmatrix lane addresses (no swizzle)
    uint32_t ahi = sb + (uint32_t)(wm * 32 + (lane & 15)) * A_STRIDE
                 + (uint32_t)((lane >> 4) << 4);
    uint32_t alo = ahi + A_LO_OFF;
    uint32_t blane = (uint32_t)(wn * 8 + (lane & 7)) * B_STRIDE
                   + (uint32_t)(((lane >> 3) & 1) << 4);

    float bv[4], b2[4];
    int bi[4];
#pragma unroll
    for (int s = 0; s < 4; ++s) { bv[s] = 3.4e38f; b2[s] = 3.4e38f; bi[s] = 0; }
    int cq = (lane & 3) * 2;

    for (int nt = 0; nt < NTILES; ++nt) {
        uint32_t buf = sb + B_OFF + (uint32_t)(nt & 1) * BTILE;
        if (nt + 1 < NTILES) {
            issue_btile(sb + B_OFF + (uint32_t)((nt + 1) & 1) * BTILE, nt + 1, tid);
            asm volatile("cp.async.wait_group 1;");
        } else {
            asm volatile("cp.async.wait_group 0;");
        }
        __syncthreads();

        float acc0[4] = {0.f, 0.f, 0.f, 0.f};
        float acc1[4] = {0.f, 0.f, 0.f, 0.f};
        uint32_t bb0 = buf + blane;

#pragma unroll
        for (int ks = 0; ks < 16; ++ks) {
            uint32_t ao = (uint32_t)(ks << 5);
            uint32_t A0h[4], A1h[4], A0l[4], A1l[4], Bh[2], Bl[2];
            LDSM_X4(A0h, ahi + ao);
            LDSM_X4(A1h, ahi + 16u * A_STRIDE + ao);
            LDSM_X4(A0l, alo + ao);
            LDSM_X4(A1l, alo + 16u * A_STRIDE + ao);
            LDSM_X2(Bh, bb0 + ao);
            LDSM_X2(Bl, bb0 + 512u + ao);
            MMA_BF16(acc0, A0h, Bh[0], Bh[1]);   // hi*hi
            MMA_BF16(acc1, A1h, Bh[0], Bh[1]);
            MMA_BF16(acc0, A0h, Bl[0], Bl[1]);   // hi*lo
            MMA_BF16(acc1, A1h, Bl[0], Bl[1]);
            MMA_BF16(acc0, A0l, Bh[0], Bh[1]);   // lo*hi
            MMA_BF16(acc1, A1l, Bh[0], Bh[1]);
        }

        // fold this 32-code tile into the running argmin (per wn slice)
        int kbase = nt * 32 + wn * 8 + cq;
        float wq0 = wsq_s[kbase], wq1 = wsq_s[kbase + 1];
#pragma unroll
        for (int s = 0; s < 4; ++s) {
            int h = s & 1;
            const float* a = (s >> 1) ? acc1 : acc0;
            float x0 = a[2 * h]     + wq0;
            float x1 = a[2 * h + 1] + wq1;
            float v = x0, v2 = 3.4e38f;
            int vi = kbase;
            amerge(v, v2, vi, x1, 3.4e38f, kbase + 1);
#pragma unroll
            for (int off = 1; off <= 2; off <<= 1) {
                float ov = __shfl_xor_sync(0xffffffffu, v, off);
                float ov2 = __shfl_xor_sync(0xffffffffu, v2, off);
                int ovi = __shfl_xor_sync(0xffffffffu, vi, off);
                amerge(v, v2, vi, ov, ov2, ovi);
            }
            amerge(bv[s], b2[s], bi[s], v, v2, vi);
        }
        __syncthreads();   // all warps done reading buf before refill
    }

    // ---- cross-warp merge over the 4 wn code-slices (fixes the R9 race) ----
    if ((lane & 3) == 0) {
#pragma unroll
        for (int s = 0; s < 4; ++s) {
            int rl = wm * 32 + (s >> 1) * 16 + (s & 1) * 8 + (lane >> 2);  // 0..63
            mv[rl * 4 + wn]  = bv[s];
            mv2[rl * 4 + wn] = b2[s];
            mvi[rl * 4 + wn] = bi[s];
        }
    }
    __syncthreads();
    if (tid < 64) {
        float v = mv[tid * 4], v2 = mv2[tid * 4];
        int vi = mvi[tid * 4];
#pragma unroll
        for (int w2 = 1; w2 < 4; ++w2)
            amerge(v, v2, vi, mv[tid * 4 + w2], mv2[tid * 4 + w2], mvi[tid * 4 + w2]);
        g_idx[m0 + tid] = vi;
        if (v2 - v < GAPT) {
            int p = atomicAdd(&g_nflag, 1);
            g_flag[p] = m0 + tid;
        }
    }
}

// ---------------- 3) exact fp32 recheck of flagged rows ----------------
#define RRB 8
__global__ __launch_bounds__(256)
void recheck_kernel(const float* __restrict__ z, const float* __restrict__ W) {
    __shared__ float zs[RRB][Dd];
    __shared__ float sbv[RRB][8];
    __shared__ int   sbi[RRB][8];
    int nf = g_nflag;
    int wid = threadIdx.x >> 5, lane = threadIdx.x & 31;
    for (int base = blockIdx.x * RRB; base < nf; base += gridDim.x * RRB) {
        int nr = min(RRB, nf - base);
        __syncthreads();
        for (int q = threadIdx.x; q < nr * Dd; q += 256) {
            int r = q >> 8, d = q & 255;
            zs[r][d] = z[(size_t)g_flag[base + r] * Dd + d];
        }
        __syncthreads();
        float bv[RRB]; int bi[RRB];
#pragma unroll
        for (int r = 0; r < RRB; ++r) { bv[r] = 3.4e38f; bi[r] = 0; }
        for (int k = wid; k < Kk; k += 8) {
            float w[8];
            const float* wr = W + (size_t)k * Dd;
#pragma unroll
            for (int j = 0; j < 8; ++j) w[j] = wr[lane + 32 * j];
            float wq = __ldg(&g_wsq[k]);
#pragma unroll
            for (int r = 0; r < RRB; ++r) {
                float p = 0.f;
#pragma unroll
                for (int j = 0; j < 8; ++j) p = fmaf(zs[r][lane + 32 * j], w[j], p);
#pragma unroll
                for (int o = 16; o; o >>= 1) p += __shfl_xor_sync(0xffffffffu, p, o);
                float dd = wq - 2.0f * p;
                if (dd < bv[r]) { bv[r] = dd; bi[r] = k; }
            }
        }
        if (lane == 0)
#pragma unroll
            for (int r = 0; r < RRB; ++r) { sbv[r][wid] = bv[r]; sbi[r][wid] = bi[r]; }
        __syncthreads();
        if (threadIdx.x < (unsigned)nr) {
            int r = threadIdx.x;
            float v = sbv[r][0]; int vi = sbi[r][0];
#pragma unroll
            for (int w2 = 1; w2 < 8; ++w2) {
                float ov = sbv[r][w2]; int oi = sbi[r][w2];
                if (ov < v || (ov == v && oi < vi)) { v = ov; vi = oi; }
            }
            g_idx[g_flag[base + r]] = vi;
        }
    }
}

// ---------------- 4) scatter dw + counts ----------------
__global__ void scatter_kernel(const float* __restrict__ z) {
    int n = (blockIdx.x * blockDim.x + threadIdx.x) >> 5;
    int lane = threadIdx.x & 31;
    int k = g_idx[n];
    const float* zr = z + (size_t)n * Dd;
    float* dr = g_dw + (size_t)k * Dd;
#pragma unroll
    for (int j = 0; j < 8; ++j)
        atomicAdd(dr + lane + 32 * j, zr[lane + 32 * j]);
    if (lane == 0) atomicAdd(&g_counts[k], 1.0f);
}

// ---------------- 5) cs EMA + smoothing + perplexity ----------------
__global__ void finalize_cs_kernel(const float* __restrict__ cs_in,
                                   float* __restrict__ out_cs,
                                   float* __restrict__ out_perp) {
    __shared__ float s1[256], s2[256];
    int t = threadIdx.x;
    float scs = 0.f, se = 0.f;
    float csr[16];
#pragma unroll
    for (int i = 0; i < 16; ++i) {
        int k = t + i * 256;
        float cnt = g_counts[k];
        float r = cs_in[k] * DECAYF + (1.0f - DECAYF) * cnt;
        csr[i] = r;
        scs += r;
        float p = cnt * (1.0f / (float)Nn);
        se += p * logf(p + 1e-10f);
    }
    s1[t] = scs; s2[t] = se;
    __syncthreads();
    for (int o = 128; o; o >>= 1) {
        if (t < o) { s1[t] += s1[t + o]; s2[t] += s2[t + o]; }
        __syncthreads();
    }
    float n = s1[0];
    float scale = n / (n + (float)Kk * EPSF);
#pragma unroll
    for (int i = 0; i < 16; ++i) {
        int k = t + i * 256;
        float cf = (csr[i] + EPSF) * scale;
        g_cs[k] = cf;
        out_cs[k] = cf;
    }
    if (t == 0) out_perp[0] = expf(-s2[0]);
}

// ---------------- 6) EMA weight + normalized codebook ----------------
__global__ void update_w_kernel(const float* __restrict__ ema,
                                float* __restrict__ out_ema,
                                float* __restrict__ out_w) {
    int i = blockIdx.x * 256 + threadIdx.x;
    float e = ema[i] * DECAYF + (1.0f - DECAYF) * g_dw[i];
    out_ema[i] = e;
    out_w[i] = e / g_cs[i >> 8];
}

// ---------------- 7) z_q gather (STE) + loss + idx ----------------
__global__ void gather_loss_kernel(const float* __restrict__ z,
                                   const float* __restrict__ w_new,
                                   float* __restrict__ out_zq,
                                   float* __restrict__ out_idx) {
    int n = (blockIdx.x * blockDim.x + threadIdx.x) >> 5;
    int lane = threadIdx.x & 31;
    int k = g_idx[n];
    const float* wr = w_new + (size_t)k * Dd;
    const float* zr = z + (size_t)n * Dd;
    float* qr = out_zq + (size_t)n * Dd;
    float part = 0.f;
#pragma unroll
    for (int j = 0; j < 8; ++j) {
        int dd = lane + 32 * j;
        float wv = wr[dd], zv = zr[dd];
        float tdiff = wv - zv;
        qr[dd] = zv + tdiff;
        part += tdiff * tdiff;
    }
#pragma unroll
    for (int o = 16; o; o >>= 1) part += __shfl_xor_sync(0xffffffffu, part, o);
    if (lane == 0) {
        out_idx[n] = (float)k;
        atomicAdd(&g_red[0], part);
    }
}

__global__ void loss_kernel(float* __restrict__ out_loss) {
    out_loss[0] = (1.0f + BETAF) * g_red[0] / (float)((size_t)Nn * Dd);
}

// ---------------- host launcher ----------------
extern "C" void kernel_launch(void* const* d_in, const int* in_sizes, int n_in,
                              void* d_out, int out_size) {
    const float* z   = (const float*)d_in[0];
    const float* W   = (const float*)d_in[1];
    const float* ema = (const float*)d_in[2];
    const float* cs  = (const float*)d_in[3];
    float* out = (float*)d_out;

    const size_t off_idx  = (size_t)Nn * Dd;
    const size_t off_loss = off_idx + Nn;
    const size_t off_perp = off_loss + 1;
    const size_t off_cs   = off_perp + 1;
    const size_t off_emaw = off_cs + Kk;
    const size_t off_w    = off_emaw + (size_t)Kk * Dd;

    void *p_counts, *p_dw, *p_red, *p_nf;
    cudaGetSymbolAddress(&p_counts, g_counts);
    cudaGetSymbolAddress(&p_dw, g_dw);
    cudaGetSymbolAddress(&p_red, g_red);
    cudaGetSymbolAddress(&p_nf, g_nflag);
    cudaMemsetAsync(p_counts, 0, Kk * sizeof(float));
    cudaMemsetAsync(p_dw, 0, (size_t)Kk * Dd * sizeof(float));
    cudaMemsetAsync(p_red, 0, 4 * sizeof(float));
    cudaMemsetAsync(p_nf, 0, sizeof(int));

    cudaFuncSetAttribute(mma_argmin_kernel,
                         cudaFuncAttributeMaxDynamicSharedMemorySize, SMEM_BYTES);

    prep_w_kernel<<<Kk, 256>>>(W);
    mma_argmin_kernel<<<Nn / 64, 256, SMEM_BYTES>>>(z);
    recheck_kernel<<<256, 256>>>(z, W);
    scatter_kernel<<<Nn / 8, 256>>>(z);
    finalize_cs_kernel<<<1, 256>>>(cs, out + off_cs, out + off_perp);
    update_w_kernel<<<(Kk * Dd) / 256, 256>>>(ema, out + off_emaw, out + off_w);
    gather_loss_kernel<<<Nn / 8, 256>>>(z, out + off_w, out, out + off_idx);
    loss_kernel<<<1, 1>>>(out + off_loss);
}

// round 12
// speedup vs baseline: 1.2959x; 1.2330x over previous
#include <cuda_runtime.h>
#include <cuda_bf16.h>
#include <cstdint>
#include <cstddef>

#define Nn 65536
#define Dd 256
#define Kk 4096
#define DECAYF 0.99f
#define BETAF 0.25f
#define EPSF 1e-5f
#define GAPT 0.5f

// ---- smem map (bytes), BM=64 rows, 64-code tiles, 1-term bf16 ----
// A_hi [0, 64*528)            = 33792
// B    [33792, 33792+2*33792) (64 codes x 528B per buffer)
// wsq  [101376, 117760)
// merge[117760, 120832): mv[64][4], mv2[64][4], mvi[64][4]
#define A_STRIDE 528u
#define B_OFF    33792u
#define B_STRIDE 528u
#define BTILE    33792u
#define WSQ_OFF  101376u
#define MRG_OFF  117760u
#define SMEM_BYTES 120832u
#define NTILES 64   // 4096 / 64 codes per tile

__device__ __forceinline__ uint32_t smem_u32(const void* p) {
    uint32_t a;
    asm("{ .reg .u64 t; cvta.to.shared.u64 t, %1; cvt.u32.u64 %0, t; }" : "=r"(a) : "l"(p));
    return a;
}
#define LDSM_X4(r, a) asm volatile( \
    "ldmatrix.sync.aligned.m8n8.x4.shared.b16 {%0,%1,%2,%3}, [%4];" \
    : "=r"((r)[0]), "=r"((r)[1]), "=r"((r)[2]), "=r"((r)[3]) : "r"(a))
#define MMA_BF16(d, a, b0, b1) asm volatile( \
    "mma.sync.aligned.m16n8k16.row.col.f32.bf16.bf16.f32 " \
    "{%0,%1,%2,%3}, {%4,%5,%6,%7}, {%8,%9}, {%0,%1,%2,%3};" \
    : "+f"((d)[0]), "+f"((d)[1]), "+f"((d)[2]), "+f"((d)[3]) \
    : "r"((a)[0]), "r"((a)[1]), "r"((a)[2]), "r"((a)[3]), "r"(b0), "r"(b1))

// ============ scratch globals ============
__device__ __align__(128) __nv_bfloat16 g_bs[(size_t)Kk * 256]; // [k][256] bf16 of -2w (hi only)
__device__ __align__(16) float g_wsq[Kk];
__device__ __align__(16) int   g_idx[Nn];
__device__ __align__(16) float g_counts[Kk];
__device__ __align__(16) float g_dw[(size_t)Kk * Dd];
__device__ __align__(16) float g_cs[Kk];
__device__ __align__(16) float g_red[4];
__device__ __align__(16) int   g_flag[Nn];
__device__ int g_nflag;

// ---------------- 1) prep: wsq + bf16 of -2W ----------------
__global__ void prep_w_kernel(const float* __restrict__ W) {
    __shared__ float s[8];
    int k = blockIdx.x, t = threadIdx.x;
    float w = W[(size_t)k * Dd + t];
    float v = w * w;
#pragma unroll
    for (int o = 16; o; o >>= 1) v += __shfl_xor_sync(0xffffffffu, v, o);
    if ((t & 31) == 0) s[t >> 5] = v;
    __syncthreads();
    if (t < 8) {
        float x = s[t];
#pragma unroll
        for (int o = 4; o; o >>= 1) x += __shfl_xor_sync(0xffu, x, o);
        if (t == 0) g_wsq[k] = x;
    }
    g_bs[(size_t)k * 256 + t] = __float2bfloat16(-2.0f * w);
}

// ---------------- 2) HMMA distance + argmin (64 rows/CTA, 1 term) ----------------
__device__ __forceinline__ void issue_btile(uint32_t bb, int nt, int tid) {
    int k0 = nt * 64;
#pragma unroll
    for (int ii = 0; ii < 8; ++ii) {
        int q = tid + ii * 256;          // 0..2047 16B chunks
        int code = q >> 5;               // 0..63
        int ci = q & 31;                 // 16B chunk within 512B payload
        const char* gp = (const char*)g_bs + (((size_t)(k0 + code)) << 9) + (ci << 4);
        uint32_t sa = bb + (uint32_t)code * B_STRIDE + (uint32_t)(ci << 4);
        asm volatile("cp.async.cg.shared.global [%0], [%1], 16;" :: "r"(sa), "l"(gp));
    }
    asm volatile("cp.async.commit_group;");
}

__device__ __forceinline__ uint32_t bpack(float a, float b) {
    __nv_bfloat162 t(__float2bfloat16(a), __float2bfloat16(b));
    return *reinterpret_cast<uint32_t*>(&t);
}

// merge (ov,ov2,ovi) into (v,v2,vi); exact ties -> lower index with gap 0 (gets flagged)
__device__ __forceinline__ void amerge(float& v, float& v2, int& vi,
                                       float ov, float ov2, int ovi) {
    if (ov < v)      { v2 = fminf(v, ov2); v = ov; vi = ovi; }
    else if (ov > v) { v2 = fminf(v2, ov); }
    else             { v2 = v; vi = min(vi, ovi); }
}

__global__ __launch_bounds__(256, 1)
void mma_argmin_kernel(const float* __restrict__ z) {
    extern __shared__ char smem[];
    uint32_t sb = smem_u32(smem);
    float* wsq_s = (float*)(smem + WSQ_OFF);
    float* mv  = (float*)(smem + MRG_OFF);          // [64][4]
    float* mv2 = mv + 256;
    int*   mvi = (int*)(mv2 + 256);
    int tid = threadIdx.x, wid = tid >> 5, lane = tid & 31;
    int m0 = blockIdx.x * 64;
    int wm = wid & 1;          // 32-row half
    int wn = wid >> 1;         // 16-code slice of the 64-code tile

    issue_btile(sb + B_OFF, 0, tid);

    // z tile -> smem bf16 (hi only), padded layout
    for (int idx = tid; idx < 64 * 64; idx += 256) {
        int row = idx >> 6, c4 = idx & 63;
        float4 q = ((const float4*)(z + ((size_t)(m0 + row) << 8)))[c4];
        uint32_t off = (uint32_t)row * A_STRIDE + (uint32_t)(c4 << 3);
        *(uint2*)(smem + off) = make_uint2(bpack(q.x, q.y), bpack(q.z, q.w));
    }
    for (int i = tid; i < Kk; i += 256) wsq_s[i] = g_wsq[i];

    // ldmatrix lane addresses (no swizzle; 528-byte strides are conflict-free)
    uint32_t ahi = sb + (uint32_t)(wm * 32 + (lane & 15)) * A_STRIDE
                 + (uint32_t)((lane >> 4) << 4);
    uint32_t bl = sb + B_OFF
                + (uint32_t)(wn * 16 + ((lane >> 4) << 3) + (lane & 7)) * B_STRIDE
                + (uint32_t)(((lane >> 3) & 1) << 4);

    float bv[4], b2[4];
    int bi[4];
#pragma unroll
    for (int s = 0; s < 4; ++s) { bv[s] = 3.4e38f; b2[s] = 3.4e38f; bi[s] = 0; }
    int cq = (lane & 3) * 2;

    for (int nt = 0; nt < NTILES; ++nt) {
        uint32_t bufo = (uint32_t)(nt & 1) * BTILE;
        if (nt + 1 < NTILES) {
            issue_btile(sb + B_OFF + (uint32_t)((nt + 1) & 1) * BTILE, nt + 1, tid);
            asm volatile("cp.async.wait_group 1;");
        } else {
            asm volatile("cp.async.wait_group 0;");
        }
        __syncthreads();

        float acc[2][2][4];
#pragma unroll
        for (int a = 0; a < 2; ++a)
#pragma unroll
            for (int b = 0; b < 2; ++b)
#pragma unroll
                for (int c = 0; c < 4; ++c) acc[a][b][c] = 0.f;
        uint32_t bb0 = bl + bufo;

#pragma unroll
        for (int ks = 0; ks < 16; ++ks) {
            uint32_t ao = (uint32_t)(ks << 5);
            uint32_t A0[4], A1[4], B[4];
            LDSM_X4(A0, ahi + ao);
            LDSM_X4(A1, ahi + 16u * A_STRIDE + ao);
            LDSM_X4(B, bb0 + ao);
            MMA_BF16(acc[0][0], A0, B[0], B[1]);
            MMA_BF16(acc[0][1], A0, B[2], B[3]);
            MMA_BF16(acc[1][0], A1, B[0], B[1]);
            MMA_BF16(acc[1][1], A1, B[2], B[3]);
        }

        // fold this 64-code tile (our 16-code slice) into the running argmin
        int kb = nt * 64 + wn * 16 + cq;
        float wq0 = wsq_s[kb],     wq1 = wsq_s[kb + 1];
        float wq8 = wsq_s[kb + 8], wq9 = wsq_s[kb + 9];
#pragma unroll
        for (int s = 0; s < 4; ++s) {
            int mi = s >> 1, h = s & 1;
            float x0 = acc[mi][0][2 * h]     + wq0;
            float x1 = acc[mi][0][2 * h + 1] + wq1;
            float x2 = acc[mi][1][2 * h]     + wq8;
            float x3 = acc[mi][1][2 * h + 1] + wq9;
            float v = x0, v2 = 3.4e38f;
            int vi = kb;
            amerge(v, v2, vi, x1, 3.4e38f, kb + 1);
            amerge(v, v2, vi, x2, 3.4e38f, kb + 8);
            amerge(v, v2, vi, x3, 3.4e38f, kb + 9);
#pragma unroll
            for (int off = 1; off <= 2; off <<= 1) {
                float ov = __shfl_xor_sync(0xffffffffu, v, off);
                float ov2 = __shfl_xor_sync(0xffffffffu, v2, off);
                int ovi = __shfl_xor_sync(0xffffffffu, vi, off);
                amerge(v, v2, vi, ov, ov2, ovi);
            }
            amerge(bv[s], b2[s], bi[s], v, v2, vi);
        }
        __syncthreads();   // all warps done reading buf before refill
    }

    // ---- cross-warp merge over the 4 wn code-slices ----
    if ((lane & 3) == 0) {
#pragma unroll
        for (int s = 0; s < 4; ++s) {
            int rl = wm * 32 + (s >> 1) * 16 + (s & 1) * 8 + (lane >> 2);  // 0..63
            mv[rl * 4 + wn]  = bv[s];
            mv2[rl * 4 + wn] = b2[s];
            mvi[rl * 4 + wn] = bi[s];
        }
    }
    __syncthreads();
    if (tid < 64) {
        float v = mv[tid * 4], v2 = mv2[tid * 4];
        int vi = mvi[tid * 4];
#pragma unroll
        for (int w2 = 1; w2 < 4; ++w2)
            amerge(v, v2, vi, mv[tid * 4 + w2], mv2[tid * 4 + w2], mvi[tid * 4 + w2]);
        g_idx[m0 + tid] = vi;
        if (v2 - v < GAPT) {
            int p = atomicAdd(&g_nflag, 1);
            g_flag[p] = m0 + tid;
        }
    }
}

// ---------------- 3) exact fp32 recheck of flagged rows ----------------
#define RRB 8
__global__ __launch_bounds__(256)
void recheck_kernel(const float* __restrict__ z, const float* __restrict__ W) {
    __shared__ float zs[RRB][Dd];
    __shared__ float sbv[RRB][8];
    __shared__ int   sbi[RRB][8];
    int nf = g_nflag;
    int wid = threadIdx.x >> 5, lane = threadIdx.x & 31;
    for (int base = blockIdx.x * RRB; base < nf; base += gridDim.x * RRB) {
        int nr = min(RRB, nf - base);
        __syncthreads();
        for (int q = threadIdx.x; q < nr * Dd; q += 256) {
            int r = q >> 8, d = q & 255;
            zs[r][d] = z[(size_t)g_flag[base + r] * Dd + d];
        }
        __syncthreads();
        float bv[RRB]; int bi[RRB];
#pragma unroll
        for (int r = 0; r < RRB; ++r) { bv[r] = 3.4e38f; bi[r] = 0; }
        for (int k = wid; k < Kk; k += 8) {
            float w[8];
            const float* wr = W + (size_t)k * Dd;
#pragma unroll
            for (int j = 0; j < 8; ++j) w[j] = wr[lane + 32 * j];
            float wq = __ldg(&g_wsq[k]);
#pragma unroll
            for (int r = 0; r < RRB; ++r) {
                float p = 0.f;
#pragma unroll
                for (int j = 0; j < 8; ++j) p = fmaf(zs[r][lane + 32 * j], w[j], p);
#pragma unroll
                for (int o = 16; o; o >>= 1) p += __shfl_xor_sync(0xffffffffu, p, o);
                float dd = wq - 2.0f * p;
                if (dd < bv[r]) { bv[r] = dd; bi[r] = k; }
            }
        }
        if (lane == 0)
#pragma unroll
            for (int r = 0; r < RRB; ++r) { sbv[r][wid] = bv[r]; sbi[r][wid] = bi[r]; }
        __syncthreads();
        if (threadIdx.x < (unsigned)nr) {
            int r = threadIdx.x;
            float v = sbv[r][0]; int vi = sbi[r][0];
#pragma unroll
            for (int w2 = 1; w2 < 8; ++w2) {
                float ov = sbv[r][w2]; int oi = sbi[r][w2];
                if (ov < v || (ov == v && oi < vi)) { v = ov; vi = oi; }
            }
            g_idx[g_flag[base + r]] = vi;
        }
    }
}

// ---------------- 4) scatter dw + counts ----------------
__global__ void scatter_kernel(const float* __restrict__ z) {
    int n = (blockIdx.x * blockDim.x + threadIdx.x) >> 5;
    int lane = threadIdx.x & 31;
    int k = g_idx[n];
    const float* zr = z + (size_t)n * Dd;
    float* dr = g_dw + (size_t)k * Dd;
#pragma unroll
    for (int j = 0; j < 8; ++j)
        atomicAdd(dr + lane + 32 * j, zr[lane + 32 * j]);
    if (lane == 0) atomicAdd(&g_counts[k], 1.0f);
}

// ---------------- 5) cs EMA + smoothing + perplexity ----------------
__global__ void finalize_cs_kernel(const float* __restrict__ cs_in,
                                   float* __restrict__ out_cs,
                                   float* __restrict__ out_perp) {
    __shared__ float s1[256], s2[256];
    int t = threadIdx.x;
    float scs = 0.f, se = 0.f;
    float csr[16];
#pragma unroll
    for (int i = 0; i < 16; ++i) {
        int k = t + i * 256;
        float cnt = g_counts[k];
        float r = cs_in[k] * DECAYF + (1.0f - DECAYF) * cnt;
        csr[i] = r;
        scs += r;
        float p = cnt * (1.0f / (float)Nn);
        se += p * logf(p + 1e-10f);
    }
    s1[t] = scs; s2[t] = se;
    __syncthreads();
    for (int o = 128; o; o >>= 1) {
        if (t < o) { s1[t] += s1[t + o]; s2[t] += s2[t + o]; }
        __syncthreads();
    }
    float n = s1[0];
    float scale = n / (n + (float)Kk * EPSF);
#pragma unroll
    for (int i = 0; i < 16; ++i) {
        int k = t + i * 256;
        float cf = (csr[i] + EPSF) * scale;
        g_cs[k] = cf;
        out_cs[k] = cf;
    }
    if (t == 0) out_perp[0] = expf(-s2[0]);
}

// ---------------- 6) EMA weight + normalized codebook ----------------
__global__ void update_w_kernel(const float* __restrict__ ema,
                                float* __restrict__ out_ema,
                                float* __restrict__ out_w) {
    int i = blockIdx.x * 256 + threadIdx.x;
    float e = ema[i] * DECAYF + (1.0f - DECAYF) * g_dw[i];
    out_ema[i] = e;
    out_w[i] = e / g_cs[i >> 8];
}

// ---------------- 7) z_q gather (STE) + loss + idx ----------------
__global__ void gather_loss_kernel(const float* __restrict__ z,
                                   const float* __restrict__ w_new,
                                   float* __restrict__ out_zq,
                                   float* __restrict__ out_idx) {
    int n = (blockIdx.x * blockDim.x + threadIdx.x) >> 5;
    int lane = threadIdx.x & 31;
    int k = g_idx[n];
    const float* wr = w_new + (size_t)k * Dd;
    const float* zr = z + (size_t)n * Dd;
    float* qr = out_zq + (size_t)n * Dd;
    float part = 0.f;
#pragma unroll
    for (int j = 0; j < 8; ++j) {
        int dd = lane + 32 * j;
        float wv = wr[dd], zv = zr[dd];
        float tdiff = wv - zv;
        qr[dd] = zv + tdiff;
        part += tdiff * tdiff;
    }
#pragma unroll
    for (int o = 16; o; o >>= 1) part += __shfl_xor_sync(0xffffffffu, part, o);
    if (lane == 0) {
        out_idx[n] = (float)k;
        atomicAdd(&g_red[0], part);
    }
}

__global__ void loss_kernel(float* __restrict__ out_loss) {
    out_loss[0] = (1.0f + BETAF) * g_red[0] / (float)((size_t)Nn * Dd);
}

// ---------------- host launcher ----------------
extern "C" void kernel_launch(void* const* d_in, const int* in_sizes, int n_in,
                              void* d_out, int out_size) {
    const float* z   = (const float*)d_in[0];
    const float* W   = (const float*)d_in[1];
    const float* ema = (const float*)d_in[2];
    const float* cs  = (const float*)d_in[3];
    float* out = (float*)d_out;

    const size_t off_idx  = (size_t)Nn * Dd;
    const size_t off_loss = off_idx + Nn;
    const size_t off_perp = off_loss + 1;
    const size_t off_cs   = off_perp + 1;
    const size_t off_emaw = off_cs + Kk;
    const size_t off_w    = off_emaw + (size_t)Kk * Dd;

    void *p_counts, *p_dw, *p_red, *p_nf;
    cudaGetSymbolAddress(&p_counts, g_counts);
    cudaGetSymbolAddress(&p_dw, g_dw);
    cudaGetSymbolAddress(&p_red, g_red);
    cudaGetSymbolAddress(&p_nf, g_nflag);
    cudaMemsetAsync(p_counts, 0, Kk * sizeof(float));
    cudaMemsetAsync(p_dw, 0, (size_t)Kk * Dd * sizeof(float));
    cudaMemsetAsync(p_red, 0, 4 * sizeof(float));
    cudaMemsetAsync(p_nf, 0, sizeof(int));

    cudaFuncSetAttribute(mma_argmin_kernel,
                         cudaFuncAttributeMaxDynamicSharedMemorySize, SMEM_BYTES);

    prep_w_kernel<<<Kk, 256>>>(W);
    mma_argmin_kernel<<<Nn / 64, 256, SMEM_BYTES>>>(z);
    recheck_kernel<<<512, 256>>>(z, W);
    scatter_kernel<<<Nn / 8, 256>>>(z);
    finalize_cs_kernel<<<1, 256>>>(cs, out + off_cs, out + off_perp);
    update_w_kernel<<<(Kk * Dd) / 256, 256>>>(ema, out + off_emaw, out + off_w);
    gather_loss_kernel<<<Nn / 8, 256>>>(z, out + off_w, out, out + off_idx);
    loss_kernel<<<1, 1>>>(out + off_loss);
}

// round 13
// speedup vs baseline: 1.5599x; 1.2038x over previous
#include <cuda_runtime.h>
#include <cuda_fp16.h>
#include <cstdint>
#include <cstddef>

#define Nn 65536
#define Dd 256
#define Kk 4096
#define DECAYF 0.99f
#define BETAF 0.25f
#define EPSF 1e-5f
#define GAPT 0.12f

// ---- smem map (bytes), BM=64 rows, 64-code tiles, fp16 1-term ----
// A [0, 64*528) = 33792 ; B [33792, 33792+2*33792) ; wsq [101376,117760)
// merge [117760, 120832)
#define A_STRIDE 528u
#define B_OFF    33792u
#define B_STRIDE 528u
#define BTILE    33792u
#define WSQ_OFF  101376u
#define MRG_OFF  117760u
#define SMEM_BYTES 120832u
#define NTILES 64   // 4096 / 64 codes per tile

__device__ __forceinline__ uint32_t smem_u32(const void* p) {
    uint32_t a;
    asm("{ .reg .u64 t; cvta.to.shared.u64 t, %1; cvt.u32.u64 %0, t; }" : "=r"(a) : "l"(p));
    return a;
}
#define LDSM_X4(r, a) asm volatile( \
    "ldmatrix.sync.aligned.m8n8.x4.shared.b16 {%0,%1,%2,%3}, [%4];" \
    : "=r"((r)[0]), "=r"((r)[1]), "=r"((r)[2]), "=r"((r)[3]) : "r"(a))
#define MMA_F16(d, a, b0, b1) asm volatile( \
    "mma.sync.aligned.m16n8k16.row.col.f32.f16.f16.f32 " \
    "{%0,%1,%2,%3}, {%4,%5,%6,%7}, {%8,%9}, {%0,%1,%2,%3};" \
    : "+f"((d)[0]), "+f"((d)[1]), "+f"((d)[2]), "+f"((d)[3]) \
    : "r"((a)[0]), "r"((a)[1]), "r"((a)[2]), "r"((a)[3]), "r"(b0), "r"(b1))

// ============ scratch globals ============
__device__ __align__(128) __half g_bs[(size_t)Kk * 256]; // [k][256] fp16 of -2w
__device__ __align__(16) float g_wsq[Kk];
__device__ __align__(16) int   g_idx[Nn];
__device__ __align__(16) float g_counts[Kk];
__device__ __align__(16) float g_dw[(size_t)Kk * Dd];
__device__ __align__(16) float g_cs[Kk];
__device__ __align__(16) float g_red[4];
__device__ __align__(16) int   g_flag[Nn];
__device__ int g_nflag;

// ---------------- 1) prep: wsq + fp16 of -2W ----------------
__global__ void prep_w_kernel(const float* __restrict__ W) {
    __shared__ float s[8];
    int k = blockIdx.x, t = threadIdx.x;
    float w = W[(size_t)k * Dd + t];
    float v = w * w;
#pragma unroll
    for (int o = 16; o; o >>= 1) v += __shfl_xor_sync(0xffffffffu, v, o);
    if ((t & 31) == 0) s[t >> 5] = v;
    __syncthreads();
    if (t < 8) {
        float x = s[t];
#pragma unroll
        for (int o = 4; o; o >>= 1) x += __shfl_xor_sync(0xffu, x, o);
        if (t == 0) g_wsq[k] = x;
    }
    g_bs[(size_t)k * 256 + t] = __float2half_rn(-2.0f * w);
}

// ---------------- 2) HMMA fp16 distance + argmin (64 rows/CTA) ----------------
__device__ __forceinline__ void issue_btile(uint32_t bb, int nt, int tid) {
    int k0 = nt * 64;
#pragma unroll
    for (int ii = 0; ii < 8; ++ii) {
        int q = tid + ii * 256;          // 0..2047 16B chunks
        int code = q >> 5;               // 0..63
        int ci = q & 31;                 // 16B chunk within 512B payload
        const char* gp = (const char*)g_bs + (((size_t)(k0 + code)) << 9) + (ci << 4);
        uint32_t sa = bb + (uint32_t)code * B_STRIDE + (uint32_t)(ci << 4);
        asm volatile("cp.async.cg.shared.global [%0], [%1], 16;" :: "r"(sa), "l"(gp));
    }
    asm volatile("cp.async.commit_group;");
}

__device__ __forceinline__ uint32_t hpack(float a, float b) {
    __half2 t(__float2half_rn(a), __float2half_rn(b));
    return *reinterpret_cast<uint32_t*>(&t);
}

// merge (ov,ov2,ovi) into (v,v2,vi); exact ties -> lower index with gap 0 (gets flagged)
__device__ __forceinline__ void amerge(float& v, float& v2, int& vi,
                                       float ov, float ov2, int ovi) {
    if (ov < v)      { v2 = fminf(v, ov2); v = ov; vi = ovi; }
    else if (ov > v) { v2 = fminf(v2, ov); }
    else             { v2 = v; vi = min(vi, ovi); }
}

__global__ __launch_bounds__(256, 1)
void mma_argmin_kernel(const float* __restrict__ z) {
    extern __shared__ char smem[];
    uint32_t sb = smem_u32(smem);
    float* wsq_s = (float*)(smem + WSQ_OFF);
    float* mv  = (float*)(smem + MRG_OFF);          // [64][4]
    float* mv2 = mv + 256;
    int*   mvi = (int*)(mv2 + 256);
    int tid = threadIdx.x, wid = tid >> 5, lane = tid & 31;
    int m0 = blockIdx.x * 64;
    int wm = wid & 1;          // 32-row half
    int wn = wid >> 1;         // 16-code slice of the 64-code tile

    issue_btile(sb + B_OFF, 0, tid);

    // z tile -> smem fp16, padded layout
    for (int idx = tid; idx < 64 * 64; idx += 256) {
        int row = idx >> 6, c4 = idx & 63;
        float4 q = ((const float4*)(z + ((size_t)(m0 + row) << 8)))[c4];
        uint32_t off = (uint32_t)row * A_STRIDE + (uint32_t)(c4 << 3);
        *(uint2*)(smem + off) = make_uint2(hpack(q.x, q.y), hpack(q.z, q.w));
    }
    for (int i = tid; i < Kk; i += 256) wsq_s[i] = g_wsq[i];

    // ldmatrix lane addresses (no swizzle; 528-byte strides are conflict-free)
    uint32_t ahi = sb + (uint32_t)(wm * 32 + (lane & 15)) * A_STRIDE
                 + (uint32_t)((lane >> 4) << 4);
    uint32_t bl = sb + B_OFF
                + (uint32_t)(wn * 16 + ((lane >> 4) << 3) + (lane & 7)) * B_STRIDE
                + (uint32_t)(((lane >> 3) & 1) << 4);

    float bv[4], b2[4];
    int bi[4];
#pragma unroll
    for (int s = 0; s < 4; ++s) { bv[s] = 3.4e38f; b2[s] = 3.4e38f; bi[s] = 0; }
    int cq = (lane & 3) * 2;

    for (int nt = 0; nt < NTILES; ++nt) {
        uint32_t bufo = (uint32_t)(nt & 1) * BTILE;
        if (nt + 1 < NTILES) {
            issue_btile(sb + B_OFF + (uint32_t)((nt + 1) & 1) * BTILE, nt + 1, tid);
            asm volatile("cp.async.wait_group 1;");
        } else {
            asm volatile("cp.async.wait_group 0;");
        }
        __syncthreads();

        float acc[2][2][4];
#pragma unroll
        for (int a = 0; a < 2; ++a)
#pragma unroll
            for (int b = 0; b < 2; ++b)
#pragma unroll
                for (int c = 0; c < 4; ++c) acc[a][b][c] = 0.f;
        uint32_t bb0 = bl + bufo;

#pragma unroll
        for (int ks = 0; ks < 16; ++ks) {
            uint32_t ao = (uint32_t)(ks << 5);
            uint32_t A0[4], A1[4], B[4];
            LDSM_X4(A0, ahi + ao);
            LDSM_X4(A1, ahi + 16u * A_STRIDE + ao);
            LDSM_X4(B, bb0 + ao);
            MMA_F16(acc[0][0], A0, B[0], B[1]);
            MMA_F16(acc[0][1], A0, B[2], B[3]);
            MMA_F16(acc[1][0], A1, B[0], B[1]);
            MMA_F16(acc[1][1], A1, B[2], B[3]);
        }

        // fold this 64-code tile (our 16-code slice) into the running argmin
        int kb = nt * 64 + wn * 16 + cq;
        float wq0 = wsq_s[kb],     wq1 = wsq_s[kb + 1];
        float wq8 = wsq_s[kb + 8], wq9 = wsq_s[kb + 9];
#pragma unroll
        for (int s = 0; s < 4; ++s) {
            int mi = s >> 1, h = s & 1;
            float x0 = acc[mi][0][2 * h]     + wq0;
            float x1 = acc[mi][0][2 * h + 1] + wq1;
            float x2 = acc[mi][1][2 * h]     + wq8;
            float x3 = acc[mi][1][2 * h + 1] + wq9;
            float v = x0, v2 = 3.4e38f;
            int vi = kb;
            amerge(v, v2, vi, x1, 3.4e38f, kb + 1);
            amerge(v, v2, vi, x2, 3.4e38f, kb + 8);
            amerge(v, v2, vi, x3, 3.4e38f, kb + 9);
#pragma unroll
            for (int off = 1; off <= 2; off <<= 1) {
                float ov = __shfl_xor_sync(0xffffffffu, v, off);
                float ov2 = __shfl_xor_sync(0xffffffffu, v2, off);
                int ovi = __shfl_xor_sync(0xffffffffu, vi, off);
                amerge(v, v2, vi, ov, ov2, ovi);
            }
            amerge(bv[s], b2[s], bi[s], v, v2, vi);
        }
        __syncthreads();   // all warps done reading buf before refill
    }

    // ---- cross-warp merge over the 4 wn code-slices ----
    if ((lane & 3) == 0) {
#pragma unroll
        for (int s = 0; s < 4; ++s) {
            int rl = wm * 32 + (s >> 1) * 16 + (s & 1) * 8 + (lane >> 2);  // 0..63
            mv[rl * 4 + wn]  = bv[s];
            mv2[rl * 4 + wn] = b2[s];
            mvi[rl * 4 + wn] = bi[s];
        }
    }
    __syncthreads();
    if (tid < 64) {
        float v = mv[tid * 4], v2 = mv2[tid * 4];
        int vi = mvi[tid * 4];
#pragma unroll
        for (int w2 = 1; w2 < 4; ++w2)
            amerge(v, v2, vi, mv[tid * 4 + w2], mv2[tid * 4 + w2], mvi[tid * 4 + w2]);
        g_idx[m0 + tid] = vi;
        if (v2 - v < GAPT) {
            int p = atomicAdd(&g_nflag, 1);
            g_flag[p] = m0 + tid;
        }
    }
}

// ---------------- 3) exact fp32 recheck of flagged rows ----------------
#define RRB 16
__global__ __launch_bounds__(256)
void recheck_kernel(const float* __restrict__ z, const float* __restrict__ W) {
    __shared__ float zs[RRB][Dd];
    __shared__ float sbv[RRB][8];
    __shared__ int   sbi[RRB][8];
    int nf = g_nflag;
    int wid = threadIdx.x >> 5, lane = threadIdx.x & 31;
    for (int base = blockIdx.x * RRB; base < nf; base += gridDim.x * RRB) {
        int nr = min(RRB, nf - base);
        __syncthreads();
        for (int q = threadIdx.x; q < nr * Dd; q += 256) {
            int r = q >> 8, d = q & 255;
            zs[r][d] = z[(size_t)g_flag[base + r] * Dd + d];
        }
        __syncthreads();
        float bv[RRB]; int bi[RRB];
#pragma unroll
        for (int r = 0; r < RRB; ++r) { bv[r] = 3.4e38f; bi[r] = 0; }
        for (int k = wid; k < Kk; k += 8) {
            float w[8];
            const float* wr = W + (size_t)k * Dd;
#pragma unroll
            for (int j = 0; j < 8; ++j) w[j] = wr[lane + 32 * j];
            float wq = __ldg(&g_wsq[k]);
#pragma unroll
            for (int r = 0; r < RRB; ++r) {
                float p = 0.f;
#pragma unroll
                for (int j = 0; j < 8; ++j) p = fmaf(zs[r][lane + 32 * j], w[j], p);
#pragma unroll
                for (int o = 16; o; o >>= 1) p += __shfl_xor_sync(0xffffffffu, p, o);
                float dd = wq - 2.0f * p;
                if (dd < bv[r]) { bv[r] = dd; bi[r] = k; }
            }
        }
        if (lane == 0)
#pragma unroll
            for (int r = 0; r < RRB; ++r) { sbv[r][wid] = bv[r]; sbi[r][wid] = bi[r]; }
        __syncthreads();
        if (threadIdx.x < (unsigned)nr) {
            int r = threadIdx.x;
            float v = sbv[r][0]; int vi = sbi[r][0];
#pragma unroll
            for (int w2 = 1; w2 < 8; ++w2) {
                float ov = sbv[r][w2]; int oi = sbi[r][w2];
                if (ov < v || (ov == v && oi < vi)) { v = ov; vi = oi; }
            }
            g_idx[g_flag[base + r]] = vi;
        }
    }
}

// ---------------- 4) scatter dw + counts ----------------
__global__ void scatter_kernel(const float* __restrict__ z) {
    int n = (blockIdx.x * blockDim.x + threadIdx.x) >> 5;
    int lane = threadIdx.x & 31;
    int k = g_idx[n];
    const float* zr = z + (size_t)n * Dd;
    float* dr = g_dw + (size_t)k * Dd;
#pragma unroll
    for (int j = 0; j < 8; ++j)
        atomicAdd(dr + lane + 32 * j, zr[lane + 32 * j]);
    if (lane == 0) atomicAdd(&g_counts[k], 1.0f);
}

// ---------------- 5) cs EMA + smoothing + perplexity ----------------
__global__ void finalize_cs_kernel(const float* __restrict__ cs_in,
                                   float* __restrict__ out_cs,
                                   float* __restrict__ out_perp) {
    __shared__ float s1[256], s2[256];
    int t = threadIdx.x;
    float scs = 0.f, se = 0.f;
    float csr[16];
#pragma unroll
    for (int i = 0; i < 16; ++i) {
        int k = t + i * 256;
        float cnt = g_counts[k];
        float r = cs_in[k] * DECAYF + (1.0f - DECAYF) * cnt;
        csr[i] = r;
        scs += r;
        float p = cnt * (1.0f / (float)Nn);
        se += p * logf(p + 1e-10f);
    }
    s1[t] = scs; s2[t] = se;
    __syncthreads();
    for (int o = 128; o; o >>= 1) {
        if (t < o) { s1[t] += s1[t + o]; s2[t] += s2[t + o]; }
        __syncthreads();
    }
    float n = s1[0];
    float scale = n / (n + (float)Kk * EPSF);
#pragma unroll
    for (int i = 0; i < 16; ++i) {
        int k = t + i * 256;
        float cf = (csr[i] + EPSF) * scale;
        g_cs[k] = cf;
        out_cs[k] = cf;
    }
    if (t == 0) out_perp[0] = expf(-s2[0]);
}

// ---------------- 6) EMA weight + normalized codebook ----------------
__global__ void update_w_kernel(const float* __restrict__ ema,
                                float* __restrict__ out_ema,
                                float* __restrict__ out_w) {
    int i = blockIdx.x * 256 + threadIdx.x;
    float e = ema[i] * DECAYF + (1.0f - DECAYF) * g_dw[i];
    out_ema[i] = e;
    out_w[i] = e / g_cs[i >> 8];
}

// ---------------- 7) z_q gather (STE) + loss + idx ----------------
__global__ void gather_loss_kernel(const float* __restrict__ z,
                                   const float* __restrict__ w_new,
                                   float* __restrict__ out_zq,
                                   float* __restrict__ out_idx) {
    int n = (blockIdx.x * blockDim.x + threadIdx.x) >> 5;
    int lane = threadIdx.x & 31;
    int k = g_idx[n];
    const float* wr = w_new + (size_t)k * Dd;
    const float* zr = z + (size_t)n * Dd;
    float* qr = out_zq + (size_t)n * Dd;
    float part = 0.f;
#pragma unroll
    for (int j = 0; j < 8; ++j) {
        int dd = lane + 32 * j;
        float wv = wr[dd], zv = zr[dd];
        float tdiff = wv - zv;
        qr[dd] = zv + tdiff;
        part += tdiff * tdiff;
    }
#pragma unroll
    for (int o = 16; o; o >>= 1) part += __shfl_xor_sync(0xffffffffu, part, o);
    if (lane == 0) {
        out_idx[n] = (float)k;
        atomicAdd(&g_red[0], part);
    }
}

__global__ void loss_kernel(float* __restrict__ out_loss) {
    out_loss[0] = (1.0f + BETAF) * g_red[0] / (float)((size_t)Nn * Dd);
}

// ---------------- host launcher ----------------
extern "C" void kernel_launch(void* const* d_in, const int* in_sizes, int n_in,
                              void* d_out, int out_size) {
    const float* z   = (const float*)d_in[0];
    const float* W   = (const float*)d_in[1];
    const float* ema = (const float*)d_in[2];
    const float* cs  = (const float*)d_in[3];
    float* out = (float*)d_out;

    const size_t off_idx  = (size_t)Nn * Dd;
    const size_t off_loss = off_idx + Nn;
    const size_t off_perp = off_loss + 1;
    const size_t off_cs   = off_perp + 1;
    const size_t off_emaw = off_cs + Kk;
    const size_t off_w    = off_emaw + (size_t)Kk * Dd;

    void *p_counts, *p_dw, *p_red, *p_nf;
    cudaGetSymbolAddress(&p_counts, g_counts);
    cudaGetSymbolAddress(&p_dw, g_dw);
    cudaGetSymbolAddress(&p_red, g_red);
    cudaGetSymbolAddress(&p_nf, g_nflag);
    cudaMemsetAsync(p_counts, 0, Kk * sizeof(float));
    cudaMemsetAsync(p_dw, 0, (size_t)Kk * Dd * sizeof(float));
    cudaMemsetAsync(p_red, 0, 4 * sizeof(float));
    cudaMemsetAsync(p_nf, 0, sizeof(int));

    cudaFuncSetAttribute(mma_argmin_kernel,
                         cudaFuncAttributeMaxDynamicSharedMemorySize, SMEM_BYTES);

    prep_w_kernel<<<Kk, 256>>>(W);
    mma_argmin_kernel<<<Nn / 64, 256, SMEM_BYTES>>>(z);
    recheck_kernel<<<256, 256>>>(z, W);
    scatter_kernel<<<Nn / 8, 256>>>(z);
    finalize_cs_kernel<<<1, 256>>>(cs, out + off_cs, out + off_perp);
    update_w_kernel<<<(Kk * Dd) / 256, 256>>>(ema, out + off_emaw, out + off_w);
    gather_loss_kernel<<<Nn / 8, 256>>>(z, out + off_w, out, out + off_idx);
    loss_kernel<<<1, 1>>>(out + off_loss);
}